// round 17
// baseline (speedup 1.0000x reference)
#include <cuda_runtime.h>
#include <cuda_fp16.h>
#include <cstdint>

// Problem constants
#define BB 4
#define TT 2048
#define CC 1024
#define HH 16
#define DD 64
#define M_ROWS (BB * TT)          // 8192
#define N_QKV  (3 * CC)           // 3072

// Scratch (device globals — allocation-free)
__device__ unsigned g_qkh[(size_t)M_ROWS * 1024];       // Q(0..511)+K(512..1023) half2 d-pairs
__device__ unsigned g_vt[(size_t)64 * 1024 * 64];       // V: [b*16+h][token-pair][d]
__device__ unsigned g_xp[(size_t)M_ROWS * CC / 2];      // x, fp16 half2 A-tiles
__device__ unsigned g_yp[(size_t)M_ROWS * CC / 2];      // attn out, fp16 half2 A-tiles
__device__ unsigned g_wqkvp[32 * 24 * 2112];            // w_qkv fp16 B-tiles
__device__ unsigned g_wprojp[32 * 8 * 2112];            // w_proj fp16 B-tiles
__device__ unsigned g_cnt1[64];                         // qkv row-block done (target 24)
__device__ unsigned g_cnt2[64];                         // yp  row-block done (target 16)
__device__ unsigned g_cntX[64];                         // xp row-block permuted (target 1)
__device__ unsigned g_cntW[32];                         // weight col-block permuted (target 1)

// ---------------------------------------------------------------------------
// Helpers
// ---------------------------------------------------------------------------
__device__ __forceinline__ float exp2a(float x) {
    float r;
    asm("ex2.approx.ftz.f32 %0, %1;" : "=f"(r) : "f"(x));
    return r;
}
__device__ __forceinline__ unsigned pack_h2(float a, float b) {
    __half2 h = __floats2half2_rn(a, b);
    return *(unsigned*)&h;
}
__device__ __forceinline__ void mma_f16(float* c, const unsigned* a, const unsigned* b) {
    asm volatile(
        "mma.sync.aligned.m16n8k16.row.col.f32.f16.f16.f32 "
        "{%0,%1,%2,%3}, {%4,%5,%6,%7}, {%8,%9}, {%0,%1,%2,%3};"
        : "+f"(c[0]), "+f"(c[1]), "+f"(c[2]), "+f"(c[3])
        : "r"(a[0]), "r"(a[1]), "r"(a[2]), "r"(a[3]),
          "r"(b[0]), "r"(b[1]));
}
__device__ __forceinline__ uint32_t smem_u32(const void* p) {
    uint32_t a;
    asm("{ .reg .u64 t; cvta.to.shared.u64 t, %1; cvt.u32.u64 %0, t; }" : "=r"(a) : "l"(p));
    return a;
}
__device__ __forceinline__ void cp16(uint32_t s, const void* g) {
    asm volatile("cp.async.cg.shared.global [%0], [%1], 16;" :: "r"(s), "l"(g));
}
__device__ __forceinline__ void cp_commit() {
    asm volatile("cp.async.commit_group;" ::: "memory");
}
__device__ __forceinline__ void wait_counter(unsigned* c, unsigned target) {
    volatile unsigned* vc = c;
    while (*vc < target) __nanosleep(64);
}

// ---------------------------------------------------------------------------
// Counter zeroing (separate launch; in-kernel reset would race on replay)
// ---------------------------------------------------------------------------
__global__ void zero_cnt_kernel()
{
    int t = threadIdx.x;
    if (t < 64) { g_cnt1[t] = 0; g_cnt2[t] = 0; g_cntX[t] = 0; }
    if (t < 32) g_cntW[t] = 0;
}

// ---------------------------------------------------------------------------
// In-mega permute bodies (same math as R14/R15 prep kernels)
// ---------------------------------------------------------------------------
__device__ __forceinline__ void permute_x_body(const float* __restrict__ in,
                                               unsigned* __restrict__ out, int mb, int tid)
{
    // row-block mb: 32 tiles (kb 0..31) x 2048 words
    for (int w = tid; w < 32 * 2048; w += 256) {
        int kb = w >> 11, ww = w & 2047;
        int row = ww >> 4, o = ww & 15;
        int q = (o & 3) * 4 + (o >> 2);
        const float* src = in + (size_t)(mb * 128 + row) * CC + kb * 32 + 2 * q;
        out[(size_t)mb * 65536 + w] = pack_h2(src[0], src[1]);
    }
    __threadfence();
    __syncthreads();
    if (tid == 0) atomicAdd(&g_cntX[mb], 1u);
}

__device__ __forceinline__ void permute_w_body(const float* __restrict__ in,
                                               unsigned* __restrict__ out,
                                               int N, int nb, int cntIdx, int tid)
{
    // col-block nb: 32 tiles (kb 0..31) x 2112 words; w = kb*2112 + ww
    for (int w = tid; w < 32 * 2112; w += 256) {
        int kb = w / 2112, ww = w - kb * 2112;
        int q = ww / 132, p = ww - q * 132;
        unsigned val = 0u;
        if (p < 128) {
            int n = nb * 128 + (p & 15) * 8 + (p >> 4);
            int k = kb * 32 + 2 * q;
            val = pack_h2(in[(size_t)k * N + n], in[(size_t)(k + 1) * N + n]);
        }
        out[(size_t)nb * (32 * 2112) + w] = val;
    }
    __threadfence();
    __syncthreads();
    if (tid == 0) atomicAdd(&g_cntW[cntIdx], 1u);
}

// ---------------------------------------------------------------------------
// fp16 GEMM body: BK=32, 4-stage cp.async, 128x128 tile, 8 warps, m16n8k16.
// ---------------------------------------------------------------------------
#define MEGA_SMEM 66560
#define QSCALE 0.18033688f   // 0.125 * log2(e)

__device__ __forceinline__ void gemm_load_stage_f16(uint32_t sb, const unsigned* Atile,
                                                    const unsigned* Btile, int st, int kb32, int tid)
{
    const unsigned* Ab = Atile + (size_t)kb32 * 2048;
    const unsigned* Bb = Btile + (size_t)kb32 * 2112;
    const uint32_t as_ = sb + st * 8192;
    const uint32_t bs_ = sb + 32768 + st * 8448;
    cp16(as_ + tid * 16, Ab + tid * 4);
    cp16(as_ + (tid + 256) * 16, Ab + (tid + 256) * 4);
    cp16(bs_ + tid * 16, Bb + tid * 4);
    cp16(bs_ + (tid + 256) * 16, Bb + (tid + 256) * 4);
    if (tid < 16)
        cp16(bs_ + (tid + 512) * 16, Bb + (tid + 512) * 4);
    cp_commit();
}

template <bool QKVOUT>
__device__ __forceinline__ void gemm_body(char* smem,
                                          const unsigned* __restrict__ Ap,
                                          const unsigned* __restrict__ Bp,
                                          const float* __restrict__ bias,
                                          float* __restrict__ Cf,
                                          unsigned* __restrict__ qkh,
                                          unsigned* __restrict__ vt,
                                          int N, int K, int bxi, int byi)
{
    const uint32_t sb = smem_u32(smem);
    const int tid  = threadIdx.x;
    const int warp = tid >> 5;
    const int lane = tid & 31;
    const int lr = lane >> 2;
    const int lc = lane & 3;
    const int wm = (warp >> 2) * 64;
    const int wn = (warp & 3) * 32;
    const int wn8 = wn >> 3;
    const int nk32 = K >> 5;

    const unsigned* Atile = Ap + (size_t)byi * nk32 * 2048;
    const unsigned* Btile = Bp + (size_t)bxi * nk32 * 2112;

    int aRd[4][2];
    #pragma unroll
    for (int mt = 0; mt < 4; mt++) {
        int rm = wm + mt * 16 + lr;
        aRd[mt][0] = rm * 16 + 4 * lc;
        aRd[mt][1] = (rm + 8) * 16 + 4 * lc;
    }
    const int bRd = lr * 16 + wn8;

    float acc[4][4][4];
    #pragma unroll
    for (int i = 0; i < 4; i++)
        #pragma unroll
        for (int j = 0; j < 4; j++)
            #pragma unroll
            for (int r = 0; r < 4; r++) acc[i][j][r] = 0.0f;

    gemm_load_stage_f16(sb, Atile, Btile, 0, 0, tid);
    gemm_load_stage_f16(sb, Atile, Btile, 1, 1, tid);
    gemm_load_stage_f16(sb, Atile, Btile, 2, 2, tid);

    for (int i = 0; i < nk32; i++) {
        const int rem = nk32 - 1 - i;
        if (rem >= 2)
            asm volatile("cp.async.wait_group 2;" ::: "memory");
        else if (rem == 1)
            asm volatile("cp.async.wait_group 1;" ::: "memory");
        else
            asm volatile("cp.async.wait_group 0;" ::: "memory");
        __syncthreads();

        if (i + 3 < nk32)
            gemm_load_stage_f16(sb, Atile, Btile, (i + 3) & 3, i + 3, tid);

        const int st = i & 3;
        const unsigned* asb = (const unsigned*)(smem + (size_t)st * 8192);
        const unsigned* bsb = (const unsigned*)(smem + 32768 + (size_t)st * 8448);

        uint4 b0 = *(const uint4*)&bsb[(lc)      * 132 + bRd];
        uint4 b1 = *(const uint4*)&bsb[(lc + 4)  * 132 + bRd];
        uint4 b2 = *(const uint4*)&bsb[(lc + 8)  * 132 + bRd];
        uint4 b3 = *(const uint4*)&bsb[(lc + 12) * 132 + bRd];

        uint4 alo[4], ahi[4];
        #pragma unroll
        for (int mt = 0; mt < 4; mt++) {
            alo[mt] = *(const uint4*)&asb[aRd[mt][0]];
            ahi[mt] = *(const uint4*)&asb[aRd[mt][1]];
        }

        #pragma unroll
        for (int mt = 0; mt < 4; mt++) {
            unsigned af[4] = { alo[mt].x, ahi[mt].x, alo[mt].y, ahi[mt].y };
            unsigned bf[2];
            bf[0] = b0.x; bf[1] = b1.x; mma_f16(acc[mt][0], af, bf);
            bf[0] = b0.y; bf[1] = b1.y; mma_f16(acc[mt][1], af, bf);
            bf[0] = b0.z; bf[1] = b1.z; mma_f16(acc[mt][2], af, bf);
            bf[0] = b0.w; bf[1] = b1.w; mma_f16(acc[mt][3], af, bf);
        }
        #pragma unroll
        for (int mt = 0; mt < 4; mt++) {
            unsigned af[4] = { alo[mt].z, ahi[mt].z, alo[mt].w, ahi[mt].w };
            unsigned bf[2];
            bf[0] = b2.x; bf[1] = b3.x; mma_f16(acc[mt][0], af, bf);
            bf[0] = b2.y; bf[1] = b3.y; mma_f16(acc[mt][1], af, bf);
            bf[0] = b2.z; bf[1] = b3.z; mma_f16(acc[mt][2], af, bf);
            bf[0] = b2.w; bf[1] = b3.w; mma_f16(acc[mt][3], af, bf);
        }
    }

    const int blockM = byi * 128;
    const int blockN = bxi * 128;

    if (!QKVOUT) {
        #pragma unroll
        for (int mt = 0; mt < 4; mt++) {
            #pragma unroll
            for (int nt = 0; nt < 4; nt++) {
                int r0 = blockM + wm + mt * 16 + lr;
                int c0 = blockN + wn + nt * 8 + lc * 2;
                float bx = bias[c0], by = bias[c0 + 1];
                *(float2*)&Cf[(size_t)r0 * N + c0] =
                    make_float2(acc[mt][nt][0] + bx, acc[mt][nt][1] + by);
                *(float2*)&Cf[(size_t)(r0 + 8) * N + c0] =
                    make_float2(acc[mt][nt][2] + bx, acc[mt][nt][3] + by);
            }
        }
    } else if (bxi < 16) {
        const float sc = (bxi < 8) ? QSCALE : 1.0f;
        #pragma unroll
        for (int mt = 0; mt < 4; mt++) {
            #pragma unroll
            for (int nt = 0; nt < 4; nt++) {
                int r0 = blockM + wm + mt * 16 + lr;
                int c0 = blockN + wn + nt * 8 + lc * 2;
                float bx = bias[c0], by = bias[c0 + 1];
                int wi = (bxi < 8) ? (c0 >> 1) : (512 + ((c0 - 1024) >> 1));
                qkh[(size_t)r0 * 1024 + wi] =
                    pack_h2((acc[mt][nt][0] + bx) * sc, (acc[mt][nt][1] + by) * sc);
                qkh[(size_t)(r0 + 8) * 1024 + wi] =
                    pack_h2((acc[mt][nt][2] + bx) * sc, (acc[mt][nt][3] + by) * sc);
            }
        }
    } else {
        __syncthreads();
        unsigned* sm32 = (unsigned*)smem;
        #pragma unroll
        for (int mt = 0; mt < 4; mt++) {
            #pragma unroll
            for (int nt = 0; nt < 4; nt++) {
                int rl = wm + mt * 16 + lr;
                int cl = wn + nt * 8 + lc * 2;
                int gc = blockN + cl;
                float bx = bias[gc], by = bias[gc + 1];
                sm32[rl * 68 + (cl >> 1)] =
                    pack_h2(acc[mt][nt][0] + bx, acc[mt][nt][1] + by);
                sm32[(rl + 8) * 68 + (cl >> 1)] =
                    pack_h2(acc[mt][nt][2] + bx, acc[mt][nt][3] + by);
            }
        }
        __syncthreads();
        const uint16_t* sm16 = (const uint16_t*)smem;
        const int hh0 = (bxi - 16) * 2;
        const int bb  = byi >> 4;
        for (int w = tid; w < 8192; w += 256) {
            int qkl = w >> 7, cl = w & 127;
            unsigned lo = sm16[(2 * qkl) * 136 + cl];
            unsigned hi = sm16[(2 * qkl + 1) * 136 + cl];
            int hh = hh0 + (cl >> 6), d = cl & 63;
            size_t qkg = (size_t)(byi & 15) * 64 + qkl;
            vt[((size_t)(bb * 16 + hh) * 1024 + qkg) * 64 + d] = lo | (hi << 16);
        }
    }
}

// ---------------------------------------------------------------------------
// fp16 MMA causal flash attention (R15-verified).
// ---------------------------------------------------------------------------
__device__ __forceinline__ void attn_load_kv(uint32_t sb, const unsigned* qkh,
                                             const unsigned* vt, size_t bT, int bh,
                                             int k0, int h, int buf, int tid)
{
    const uint32_t kbase = sb + buf * 18432;
    #pragma unroll
    for (int i = 0; i < 2; i++) {
        int c = tid + i * 256;
        int key = c >> 3, cw = c & 7;
        cp16(kbase + key * 144 + cw * 16,
             qkh + (bT + k0 + key) * 1024 + 512 + h * 32 + cw * 4);
    }
    #pragma unroll
    for (int i = 0; i < 2; i++) {
        int c = tid + i * 256;
        int qk = c >> 4, cw = c & 15;
        cp16(kbase + 9216 + qk * 288 + cw * 16,
             vt + ((size_t)bh * 1024 + (k0 >> 1) + qk) * 64 + cw * 4);
    }
    cp_commit();
}

__device__ __forceinline__ void attn_body(char* smemc, const unsigned* __restrict__ qkh,
                                          const unsigned* __restrict__ vt,
                                          unsigned* __restrict__ yp, int qb, int bh)
{
    unsigned* kvmem = (unsigned*)smemc;
    const uint32_t sb = smem_u32(kvmem);

    const int tid  = threadIdx.x;
    const int warp = tid >> 5;
    const int lane = tid & 31;
    const int lr = lane >> 2;
    const int lc = lane & 3;

    const int b  = bh >> 4;
    const int h  = bh & 15;
    const int q0 = qb * 128;
    const size_t bT = (size_t)b * TT;

    if (tid == 0) {
        for (int j = 0; j <= qb; j++)
            wait_counter(&g_cnt1[b * 16 + j], 24u);
        __threadfence();
    }
    __syncthreads();

    unsigned qa[4][4];
    {
        const unsigned* Qlo = qkh + (bT + q0 + warp * 16 + lr) * 1024 + h * 32;
        const unsigned* Qhi = Qlo + 8 * 1024;
        #pragma unroll
        for (int s = 0; s < 4; s++) {
            int q = 8 * s + lc;
            qa[s][0] = Qlo[q];
            qa[s][1] = Qhi[q];
            qa[s][2] = Qlo[q + 4];
            qa[s][3] = Qhi[q + 4];
        }
    }

    float O[8][4];
    #pragma unroll
    for (int nt = 0; nt < 8; nt++)
        #pragma unroll
        for (int r = 0; r < 4; r++) O[nt][r] = 0.0f;

    float l_lo = 0.0f, l_hi = 0.0f;
    const int ktmax = 2 * qb + 1;

    attn_load_kv(sb, qkh, vt, bT, bh, 0, h, 0, tid);

    for (int kt = 0; kt <= ktmax; kt++) {
        const int buf = kt & 1;
        asm volatile("cp.async.wait_group 0;" ::: "memory");
        __syncthreads();
        if (kt < ktmax)
            attn_load_kv(sb, qkh, vt, bT, bh, (kt + 1) * 64, h, buf ^ 1, tid);

        const int base = q0 + warp * 16 - kt * 64;
        if (base >= 0) {
            unsigned* Kn  = kvmem + buf * 4608;
            unsigned* Vsp = Kn + 2304;
            const int blim = base + 15;

            float s[8][4];
            #pragma unroll
            for (int nt = 0; nt < 8; nt++)
                #pragma unroll
                for (int r = 0; r < 4; r++) s[nt][r] = 0.0f;

            #pragma unroll
            for (int st = 0; st < 4; st++) {
                #pragma unroll
                for (int nt = 0; nt < 8; nt++) {
                    if (nt * 8 <= blim) {
                        const int kr = (nt * 8 + lr) * 36 + 8 * st + lc;
                        unsigned bfr[2];
                        bfr[0] = Kn[kr];
                        bfr[1] = Kn[kr + 4];
                        mma_f16(s[nt], qa[st], bfr);
                    }
                }
            }

            if (base < 64) {
                #pragma unroll
                for (int nt = 0; nt < 8; nt++) {
                    int kcol = nt * 8 + 2 * lc;
                    if (kcol     > base + lr)     s[nt][0] = -1e30f;
                    if (kcol + 1 > base + lr)     s[nt][1] = -1e30f;
                    if (kcol     > base + lr + 8) s[nt][2] = -1e30f;
                    if (kcol + 1 > base + lr + 8) s[nt][3] = -1e30f;
                }
            }

            unsigned ph[8][2];
            float suml = 0.0f, sumh = 0.0f;
            #pragma unroll
            for (int nt = 0; nt < 8; nt++) {
                float e0 = exp2a(s[nt][0]);
                float e1 = exp2a(s[nt][1]);
                float e2 = exp2a(s[nt][2]);
                float e3 = exp2a(s[nt][3]);
                ph[nt][0] = pack_h2(e0, e1);
                ph[nt][1] = pack_h2(e2, e3);
                suml += e0 + e1;
                sumh += e2 + e3;
            }
            suml += __shfl_xor_sync(0xffffffffu, suml, 1);
            suml += __shfl_xor_sync(0xffffffffu, suml, 2);
            sumh += __shfl_xor_sync(0xffffffffu, sumh, 1);
            sumh += __shfl_xor_sync(0xffffffffu, sumh, 2);
            l_lo += suml;
            l_hi += sumh;

            #pragma unroll
            for (int st = 0; st < 4; st++) {
                if (st * 16 <= blim) {
                    unsigned af[4] = { ph[2 * st][0], ph[2 * st][1],
                                       ph[2 * st + 1][0], ph[2 * st + 1][1] };
                    const int vr = (8 * st + lc) * 72;
                    #pragma unroll
                    for (int nt = 0; nt < 8; nt++) {
                        unsigned bfr[2];
                        bfr[0] = Vsp[vr + nt * 8 + lr];
                        bfr[1] = Vsp[vr + 288 + nt * 8 + lr];
                        mma_f16(O[nt], af, bfr);
                    }
                }
            }
        }
    }

    const float il = 1.0f / l_lo;
    const float ih = 1.0f / l_hi;
    {
        const int grL = (int)bT + q0 + warp * 16 + lr;
        const int grH = grL + 8;
        const int mbL = grL >> 7, rowL = grL & 127;
        const int mbH = grH >> 7, rowH = grH & 127;
        unsigned* baseL = yp + (size_t)(mbL * 32) * 2048 + rowL * 16;
        unsigned* baseH = yp + (size_t)(mbH * 32) * 2048 + rowH * 16;
        #pragma unroll
        for (int nt = 0; nt < 8; nt++) {
            int qg = h * 32 + nt * 4 + lc;
            int kb32 = qg >> 4;
            int qq = qg & 15;
            int o = ((qq & 3) << 2) + (qq >> 2);
            baseL[(size_t)kb32 * 2048 + o] = pack_h2(O[nt][0] * il, O[nt][1] * il);
            baseH[(size_t)kb32 * 2048 + o] = pack_h2(O[nt][2] * ih, O[nt][3] * ih);
        }
    }

    __threadfence();
    __syncthreads();
    if (tid == 0) atomicAdd(&g_cnt2[b * 16 + qb], 1u);
}

// ---------------------------------------------------------------------------
// Mega kernel: permutes (0..95) -> GEMM1 (96..1631) -> attention (1632..2655)
// -> GEMM2 (2656..3167). Counter-gated dataflow; in-order dispatch -> no deadlock.
// ---------------------------------------------------------------------------
__global__ __launch_bounds__(256, 2)
void mega_kernel(const float* __restrict__ x, const float* __restrict__ w_qkv,
                 const float* __restrict__ w_proj,
                 unsigned* __restrict__ xp, unsigned* __restrict__ wqkvp,
                 unsigned* __restrict__ wprojp,
                 const float* __restrict__ b_qkv, unsigned* __restrict__ qkh,
                 unsigned* __restrict__ vt, unsigned* __restrict__ yp,
                 const float* __restrict__ b_proj, float* __restrict__ out)
{
    extern __shared__ char smem[];
    const int id = blockIdx.x;
    const int tid = threadIdx.x;

    if (id < 64) {
        permute_x_body(x, xp, id, tid);
    } else if (id < 88) {
        permute_w_body(w_qkv, wqkvp, N_QKV, id - 64, id - 64, tid);
    } else if (id < 96) {
        permute_w_body(w_proj, wprojp, CC, id - 88, 24 + (id - 88), tid);
    } else if (id < 1632) {
        const int t = id - 96;
        const int bx = t % 24, by = t / 24;
        if (tid == 0) {
            wait_counter(&g_cntX[by], 1u);
            wait_counter(&g_cntW[bx], 1u);
            __threadfence();
        }
        __syncthreads();
        gemm_body<true>(smem, xp, wqkvp, b_qkv, nullptr, qkh, vt, N_QKV, CC, bx, by);
        __threadfence();
        __syncthreads();
        if (tid == 0) atomicAdd(&g_cnt1[by], 1u);
    } else if (id < 2656) {
        const int t = id - 1632;
        const int qb = 15 - (t & 15);
        const int bh = t >> 4;
        attn_body(smem, qkh, vt, yp, qb, bh);
    } else {
        const int t = id - 2656;
        const int bx = t & 7, by = t >> 3;
        if (tid == 0) {
            wait_counter(&g_cntW[24 + bx], 1u);
            wait_counter(&g_cnt2[by], 16u);
            __threadfence();
        }
        __syncthreads();
        gemm_body<false>(smem, yp, wprojp, b_proj, out, nullptr, nullptr, CC, CC, bx, by);
    }
}

// ---------------------------------------------------------------------------
// Launch
// ---------------------------------------------------------------------------
extern "C" void kernel_launch(void* const* d_in, const int* in_sizes, int n_in,
                              void* d_out, int out_size)
{
    const float* x      = (const float*)d_in[0];
    const float* w_qkv  = (const float*)d_in[1];
    const float* b_qkv  = (const float*)d_in[2];
    const float* w_proj = (const float*)d_in[3];
    const float* b_proj = (const float*)d_in[4];
    float* out = (float*)d_out;

    unsigned *qkh, *vt, *xp, *yp, *wqkvp, *wprojp;
    cudaGetSymbolAddress((void**)&qkh,    g_qkh);
    cudaGetSymbolAddress((void**)&vt,     g_vt);
    cudaGetSymbolAddress((void**)&xp,     g_xp);
    cudaGetSymbolAddress((void**)&yp,     g_yp);
    cudaGetSymbolAddress((void**)&wqkvp,  g_wqkvp);
    cudaGetSymbolAddress((void**)&wprojp, g_wprojp);

    cudaFuncSetAttribute(mega_kernel, cudaFuncAttributeMaxDynamicSharedMemorySize, MEGA_SMEM);

    // 0) Zero dependency counters (separate launch; in-kernel reset would race on replay)
    zero_cnt_kernel<<<1, 64>>>();

    // 1) Fully fused permutes + GEMM1 + attention + GEMM2
    mega_kernel<<<3168, 256, MEGA_SMEM>>>(x, w_qkv, w_proj, xp, wqkvp, wprojp,
                                          b_qkv, qkh, vt, yp, b_proj, out);
}